// round 9
// baseline (speedup 1.0000x reference)
#include <cuda_runtime.h>
#include <cuda_bf16.h>
#include <cstdint>

#define Bv 256
#define Mv 1024
#define Dv 128
#define Nv 26
#define EP 32   // padded per-row stride for emission scratch

// ---------------- scratch ----------------
__device__ __nv_bfloat16 g_e[(size_t)Bv * Mv * EP];   // 16 MB emissions (bf16, padded)
__device__ float g_pF[Bv * EP];                 // fwd pre-emission vec at i=512
__device__ float g_pB[Bv * EP];                 // bwd post-emission vec at i=512
__device__ float g_sF[Bv], g_sB[Bv];            // log-scales
__device__ float g_u[Bv];                       // unnormalized path scores

__device__ __forceinline__ void ffma2(unsigned long long &d,
                                      unsigned long long a,
                                      unsigned long long b) {
    asm("fma.rn.f32x2 %0, %1, %2, %0;" : "+l"(d) : "l"(a), "l"(b));
}
__device__ __forceinline__ void fadd2(unsigned long long &d, unsigned long long a) {
    asm("add.rn.f32x2 %0, %0, %1;" : "+l"(d) : "l"(a));
}
__device__ __forceinline__ unsigned long long packf2(float lo, float hi) {
    unsigned long long r;
    asm("mov.b64 %0, {%1, %2};" : "=l"(r) : "f"(lo), "f"(hi));
    return r;
}

// ---------------- Kernel 1: emissions e = X @ W^T via HMMA bf16 ----------------
// 64-row tiles, 128-thread blocks (4 warps x 16 rows x 32 labels), 26 KB smem
// => 8 blocks/SM for load/compute overlap across blocks.
__global__ void __launch_bounds__(128) emis_kernel(const float* __restrict__ X,
                                                   const float* __restrict__ W) {
    __shared__ __align__(16) unsigned short sX[64 * 136];    // 17408 B
    __shared__ __align__(16) unsigned short sW[32 * 136];    //  8704 B
    const int tid  = threadIdx.x;
    const int warp = tid >> 5, lane = tid & 31;
    const int g = lane >> 2, t = lane & 3;

    // W: 26x128 fp32 -> bf16, zero-pad labels 26..31
    for (int i = tid; i < 1664; i += 128) {
        const float2 w2 = reinterpret_cast<const float2*>(W)[i];
        const int row = i >> 6;
        const int cp  = i & 63;
        unsigned u;
        asm("cvt.rn.bf16x2.f32 %0, %1, %2;" : "=r"(u) : "f"(w2.y), "f"(w2.x));
        *reinterpret_cast<unsigned*>(&sW[row * 136 + cp * 2]) = u;
    }
    for (int i = tid; i < 6 * 68; i += 128)
        *reinterpret_cast<unsigned*>(&sW[26 * 136 + i * 2]) = 0;

    // X tile: 64 rows x 128 dims, coalesced float4 -> two bf16x2
    const float4* __restrict__ Xv =
        reinterpret_cast<const float4*>(X) + (size_t)blockIdx.x * 64 * 32;
    for (int i = tid; i < 64 * 32; i += 128) {
        const float4 v = __ldcs(&Xv[i]);
        const int row = i >> 5, q = i & 31;
        unsigned u0, u1;
        asm("cvt.rn.bf16x2.f32 %0, %1, %2;" : "=r"(u0) : "f"(v.y), "f"(v.x));
        asm("cvt.rn.bf16x2.f32 %0, %1, %2;" : "=r"(u1) : "f"(v.w), "f"(v.z));
        *reinterpret_cast<uint2*>(&sX[row * 136 + q * 4]) = make_uint2(u0, u1);
    }
    __syncthreads();

    float d[4][4];
#pragma unroll
    for (int n = 0; n < 4; n++)
#pragma unroll
        for (int r = 0; r < 4; r++) d[n][r] = 0.0f;

    const unsigned* sXu = reinterpret_cast<const unsigned*>(sX);
    const unsigned* sWu = reinterpret_cast<const unsigned*>(sW);
    const int arow  = 16 * warp + g;
    const int abase = (arow * 272 + t * 4) >> 2;

#pragma unroll
    for (int k = 0; k < 8; k++) {
        const unsigned a0 = sXu[abase + k * 8];
        const unsigned a1 = sXu[abase + k * 8 + 544];   // +8 rows
        const unsigned a2 = sXu[abase + k * 8 + 4];     // +8 dims
        const unsigned a3 = sXu[abase + k * 8 + 548];
#pragma unroll
        for (int n = 0; n < 4; n++) {
            const int bbase = ((n * 8 + g) * 272 + k * 32 + t * 4) >> 2;
            const unsigned b0 = sWu[bbase];
            const unsigned b1 = sWu[bbase + 4];
            asm volatile(
                "mma.sync.aligned.m16n8k16.row.col.f32.bf16.bf16.f32 "
                "{%0,%1,%2,%3}, {%4,%5,%6,%7}, {%8,%9}, {%0,%1,%2,%3};"
                : "+f"(d[n][0]), "+f"(d[n][1]), "+f"(d[n][2]), "+f"(d[n][3])
                : "r"(a0), "r"(a1), "r"(a2), "r"(a3), "r"(b0), "r"(b1));
        }
    }

    unsigned short* eout =
        reinterpret_cast<unsigned short*>(g_e) + (size_t)blockIdx.x * 64 * EP;
    const int r0 = 16 * warp + g;
#pragma unroll
    for (int n = 0; n < 4; n++) {
        const int c = n * 8 + 2 * t;
        unsigned u01, u23;
        asm("cvt.rn.bf16x2.f32 %0, %1, %2;" : "=r"(u01) : "f"(d[n][1]), "f"(d[n][0]));
        asm("cvt.rn.bf16x2.f32 %0, %1, %2;" : "=r"(u23) : "f"(d[n][3]), "f"(d[n][2]));
        *reinterpret_cast<unsigned*>(&eout[(size_t)r0 * EP + c]) = u01;
        *reinterpret_cast<unsigned*>(&eout[(size_t)(r0 + 8) * EP + c]) = u23;
    }
}

// ---------------- Kernel 2: fwd/bwd scan + parallel unnorm gather ----------------
// Register-only step: f scalar per lane; 26 SHFL broadcasts; pair-dot matvec via
// 13 fma.rn.f32x2 against per-lane packed T' column pairs. No smem, no syncwarp.
static __device__ __forceinline__ float mv26r(float f,
                                              const unsigned long long* tp) {
    const unsigned FULL = 0xffffffffu;
    const float r0  = __shfl_sync(FULL, f, 0);
    const float r1  = __shfl_sync(FULL, f, 1);
    const float r2  = __shfl_sync(FULL, f, 2);
    const float r3  = __shfl_sync(FULL, f, 3);
    const float r4  = __shfl_sync(FULL, f, 4);
    const float r5  = __shfl_sync(FULL, f, 5);
    const float r6  = __shfl_sync(FULL, f, 6);
    const float r7  = __shfl_sync(FULL, f, 7);
    const float r8  = __shfl_sync(FULL, f, 8);
    const float r9  = __shfl_sync(FULL, f, 9);
    const float r10 = __shfl_sync(FULL, f, 10);
    const float r11 = __shfl_sync(FULL, f, 11);
    const float r12 = __shfl_sync(FULL, f, 12);
    const float r13 = __shfl_sync(FULL, f, 13);
    const float r14 = __shfl_sync(FULL, f, 14);
    const float r15 = __shfl_sync(FULL, f, 15);
    const float r16 = __shfl_sync(FULL, f, 16);
    const float r17 = __shfl_sync(FULL, f, 17);
    const float r18 = __shfl_sync(FULL, f, 18);
    const float r19 = __shfl_sync(FULL, f, 19);
    const float r20 = __shfl_sync(FULL, f, 20);
    const float r21 = __shfl_sync(FULL, f, 21);
    const float r22 = __shfl_sync(FULL, f, 22);
    const float r23 = __shfl_sync(FULL, f, 23);
    const float r24 = __shfl_sync(FULL, f, 24);
    const float r25 = __shfl_sync(FULL, f, 25);
    unsigned long long a0 = 0, a1 = 0, a2 = 0, a3 = 0;
    ffma2(a0, packf2(r0,  r1),  tp[0]);
    ffma2(a1, packf2(r2,  r3),  tp[1]);
    ffma2(a2, packf2(r4,  r5),  tp[2]);
    ffma2(a3, packf2(r6,  r7),  tp[3]);
    ffma2(a0, packf2(r8,  r9),  tp[4]);
    ffma2(a1, packf2(r10, r11), tp[5]);
    ffma2(a2, packf2(r12, r13), tp[6]);
    ffma2(a3, packf2(r14, r15), tp[7]);
    ffma2(a0, packf2(r16, r17), tp[8]);
    ffma2(a1, packf2(r18, r19), tp[9]);
    ffma2(a2, packf2(r20, r21), tp[10]);
    ffma2(a3, packf2(r22, r23), tp[11]);
    ffma2(a0, packf2(r24, r25), tp[12]);
    fadd2(a0, a1); fadd2(a2, a3); fadd2(a0, a2);
    float lo, hi;
    asm("mov.b64 {%0, %1}, %2;" : "=f"(lo), "=f"(hi) : "l"(a0));
    return lo + hi;
}

__global__ void __launch_bounds__(192) scan_kernel(const int* __restrict__ labels,
                                                   const float* __restrict__ T) {
    const int warp = threadIdx.x >> 5;
    const int lane = threadIdx.x & 31;
    const unsigned FULL = 0xffffffffu;

    if (warp >= 4) {
        // unnorm gather: fully parallel over positions
        const int s = blockIdx.x * 2 + (warp - 4);
        const int* __restrict__ lab = labels + s * Mv;
        const __nv_bfloat16* __restrict__ eb = g_e + (size_t)s * Mv * EP;
        float un = 0.0f;
#pragma unroll 4
        for (int k = 0; k < 32; k++) {
            const int i = k * 32 + lane;
            const int y = __ldg(&lab[i]);
            float v = __bfloat162float(eb[(size_t)i * EP + y]);
            if (i < Mv - 1)
                v += __ldg(&T[y * Nv + __ldg(&lab[i + 1])]);
            un += v;
        }
#pragma unroll
        for (int o = 16; o; o >>= 1) un += __shfl_xor_sync(FULL, un, o);
        if (lane == 0) g_u[s] = un;
        return;
    }

    const int s   = blockIdx.x * 2 + (warp >> 1);
    const int dir = warp & 1;
    const __nv_bfloat16* __restrict__ eseq = g_e + (size_t)s * Mv * EP + lane;

    unsigned long long tp[13];      // packed T' column pairs for this lane's row
    float epE[8];                   // pre-exponentiated emissions ring
    float carry = 1.0f;
    int   eAcc = 0;

    if (dir == 0) {
        // forward: f_i = expE_i * (expT^T f_{i-1}); i=1..512
#pragma unroll
        for (int k = 0; k < 13; k++)
            tp[k] = (lane < Nv)
                ? packf2(__expf(__ldg(&T[(2 * k) * Nv + lane])),
                         __expf(__ldg(&T[(2 * k + 1) * Nv + lane])))
                : 0ull;

        const float e0 = __bfloat162float(eseq[0]);
        float f = (lane < Nv) ? __expf(e0) : 0.0f;
#pragma unroll
        for (int k = 0; k < 8; k++)
            epE[k] = __expf(__bfloat162float(eseq[(size_t)(1 + k) * EP]));

        float msum = 0.0f;
        for (int gi = 0; gi < 64; gi++) {
#pragma unroll
            for (int j = 0; j < 8; j++) {
                const int i = 1 + gi * 8 + j;
                const float expE = epE[j] * carry;
                carry = 1.0f;
                epE[j] = __expf(__bfloat162float(eseq[(size_t)(i + 8) * EP]));
                msum = mv26r(f, tp);
                f = msum * expE;
                if (j == 7 && gi != 63) {
                    const unsigned mb = __reduce_max_sync(FULL, __float_as_uint(f));
                    const unsigned pb = mb & 0x7f800000u;
                    carry = __uint_as_float(0x7f000000u - pb);   // exact 2^(127-E)
                    eAcc += (int)(pb >> 23) - 127;
                }
            }
        }
        g_pF[s * EP + lane] = msum;                          // pre-emission u_512
        if (lane == 0) g_sF[s] = (float)eAcc * 0.6931471805599453f;
    } else {
        // backward (h-form): h_1023 = expE_1023; h_i = expE_i*(expT h_{i+1}); i=1022..512
#pragma unroll
        for (int k = 0; k < 13; k++)
            tp[k] = (lane < Nv)
                ? packf2(__expf(__ldg(&T[lane * Nv + 2 * k])),
                         __expf(__ldg(&T[lane * Nv + 2 * k + 1])))
                : 0ull;

        const float e1023 = __bfloat162float(eseq[(size_t)1023 * EP]);
        float h = (lane < Nv) ? __expf(e1023) : 0.0f;
#pragma unroll
        for (int k = 0; k < 8; k++)
            epE[k] = __expf(__bfloat162float(eseq[(size_t)(1022 - k) * EP]));

        // prologue: 7 steps, i = 1022..1016 (slots 0..6)
#pragma unroll
        for (int j = 0; j < 7; j++) {
            const int i = 1022 - j;
            const float expE = epE[j];
            epE[j] = __expf(__bfloat162float(eseq[(size_t)(i - 8) * EP]));
            h = mv26r(h, tp) * expE;
        }
        {
            const unsigned mb = __reduce_max_sync(FULL, __float_as_uint(h));
            const unsigned pb = mb & 0x7f800000u;
            carry = __uint_as_float(0x7f000000u - pb);
            eAcc += (int)(pb >> 23) - 127;
        }
        // 63 groups of 8: i = 1015..512
        for (int gi = 0; gi < 63; gi++) {
#pragma unroll
            for (int j = 0; j < 8; j++) {
                const int i = 1015 - gi * 8 - j;
                const int sl = (j + 7) & 7;
                const float expE = epE[sl] * carry;
                carry = 1.0f;
                epE[sl] = __expf(__bfloat162float(eseq[(size_t)(i - 8) * EP]));
                h = mv26r(h, tp) * expE;
                if (j == 7 && gi != 62) {
                    const unsigned mb = __reduce_max_sync(FULL, __float_as_uint(h));
                    const unsigned pb = mb & 0x7f800000u;
                    carry = __uint_as_float(0x7f000000u - pb);
                    eAcc += (int)(pb >> 23) - 127;
                }
            }
        }
        g_pB[s * EP + lane] = h;                             // h_512
        if (lane == 0) g_sB[s] = (float)eAcc * 0.6931471805599453f;
    }
}

// ---------------- Kernel 3: combine ----------------
__global__ void __launch_bounds__(256) combine_kernel(float* __restrict__ out) {
    __shared__ float red[256];
    const int s = threadIdx.x;

    float z = 0.0f;
#pragma unroll
    for (int b = 0; b < Nv; b++)
        z += g_pF[s * EP + b] * g_pB[s * EP + b];

    red[s] = g_u[s] - (logf(z) + g_sF[s] + g_sB[s]);
    __syncthreads();
#pragma unroll
    for (int o = 128; o; o >>= 1) {
        if (s < o) red[s] += red[s + o];
        __syncthreads();
    }
    if (s == 0) out[0] = red[0] * (1.0f / Bv);
}

// ---------------- entry point ----------------
extern "C" void kernel_launch(void* const* d_in, const int* in_sizes, int n_in,
                              void* d_out, int out_size) {
    const float* X      = (const float*)d_in[0];
    const int*   labels = (const int*)  d_in[1];
    const float* W      = (const float*)d_in[2];
    const float* T      = (const float*)d_in[3];
    float* out = (float*)d_out;

    emis_kernel<<<(Bv * Mv) / 64, 128>>>(X, W);
    scan_kernel<<<Bv / 2, 192>>>(labels, T);
    combine_kernel<<<1, 256>>>(out);
}